// round 9
// baseline (speedup 1.0000x reference)
#include <cuda_runtime.h>

#define BLOCK 256
#define EPB   64        // elements per block (4 threads per element)
#define TSEQ  200
#define NELEM 32768

typedef unsigned long long u64;

// ---- device scratch (sanctioned: no allocation APIs) ----
__device__ float g_h2[NELEM * 800];   // phys-permuted h2 features
__device__ u64   g_wp[12800];         // packed+permuted Wout: [800 c][4 r][4 q]

// ---- tanh.approx-based activations ----
__device__ __forceinline__ float tanha_(float x) {
    float y; asm("tanh.approx.f32 %0, %1;" : "=f"(y) : "f"(x)); return y;
}

// ---- packed f32x2 ops ----
__device__ __forceinline__ u64 fma2(u64 a, u64 b, u64 c) {
    u64 d; asm("fma.rn.f32x2 %0, %1, %2, %3;" : "=l"(d) : "l"(a), "l"(b), "l"(c));
    return d;
}
__device__ __forceinline__ u64 pack2(float lo, float hi) {
    u64 r; asm("mov.b64 %0, {%1, %2};" : "=l"(r) : "f"(lo), "f"(hi)); return r;
}
__device__ __forceinline__ void unpack2(float& lo, float& hi, u64 v) {
    asm("mov.b64 {%0, %1}, %2;" : "=f"(lo), "=f"(hi) : "l"(v));
}

// =====================  kernel 0: pack + permute Wout  =====================
// phys feature p holds logical feature f = (p&~3) | ((p&3) ^ ((p>>2)&3)).
// entry idx = c*16 + r*4 + q : rows (7r+2q, 7r+2q+1) of Wout at logical col f(c).
__global__ void repack_kernel(const float* __restrict__ Wout) {
    int idx = blockIdx.x * blockDim.x + threadIdx.x;
    if (idx >= 12800) return;
    int c = idx >> 4, r4 = (idx >> 2) & 3, q = idx & 3;
    int f = (c & ~3) | ((c & 3) ^ ((c >> 2) & 3));
    int row0 = 7 * r4 + 2 * q;                 // q=3 hi is dummy
    float lo = Wout[row0 * 800 + f];
    float hi = (q < 3) ? Wout[(row0 + 1) * 800 + f] : 0.0f;
    g_wp[idx] = pack2(lo, hi);
}

// =====================  kernel 1: fused 2-layer LSTM  =====================
__device__ __forceinline__ float unit_step(
    const u64* __restrict__ inA, const u64* __restrict__ inB,
    const u64* __restrict__ wIF, const u64* __restrict__ wGO,
    u64 bIF, u64 bGO, float& c)
{
    u64 gIF = bIF, gGO = bGO;
    #pragma unroll
    for (int in = 0; in < 4; in++) {
        gIF = fma2(inA[in], wIF[in], gIF);
        gGO = fma2(inA[in], wGO[in], gGO);
    }
    #pragma unroll
    for (int in = 0; in < 4; in++) {
        gIF = fma2(inB[in], wIF[4 + in], gIF);
        gGO = fma2(inB[in], wGO[4 + in], gGO);
    }
    float iv, fv, gv, ov;
    unpack2(iv, fv, gIF);
    unpack2(gv, ov, gGO);
    float ti = tanha_(iv), tf = tanha_(fv), tg = tanha_(gv), to = tanha_(ov);
    float si = fmaf(ti, 0.5f, 0.5f);
    float sf = fmaf(tf, 0.5f, 0.5f);
    float so = fmaf(to, 0.5f, 0.5f);
    c = fmaf(sf, c, si * tg);
    return so * tanha_(c);
}

__global__ void __launch_bounds__(BLOCK, 2) lstm_kernel(
    const float* __restrict__ x,
    const float* __restrict__ Wih0, const float* __restrict__ Whh0,
    const float* __restrict__ bih0, const float* __restrict__ bhh0,
    const float* __restrict__ Wih1, const float* __restrict__ Whh1,
    const float* __restrict__ bih1, const float* __restrict__ bhh1)
{
    const int tid  = threadIdx.x;
    const int r    = tid & 3;
    const int elem = blockIdx.x * EPB + (tid >> 2);

    // gate weights -> registers, 0.5-prescaled for sigmoid gates
    u64 wIF0[8], wGO0[8], wIF1[8], wGO1[8];
    #pragma unroll
    for (int in = 0; in < 4; in++) {
        int cs = r ^ in;
        wIF0[in]     = pack2(0.5f * Wih0[(0  + r) * 4 + in], 0.5f * Wih0[(4  + r) * 4 + in]);
        wGO0[in]     = pack2(       Wih0[(8  + r) * 4 + in], 0.5f * Wih0[(12 + r) * 4 + in]);
        wIF0[4 + in] = pack2(0.5f * Whh0[(0  + r) * 4 + cs], 0.5f * Whh0[(4  + r) * 4 + cs]);
        wGO0[4 + in] = pack2(       Whh0[(8  + r) * 4 + cs], 0.5f * Whh0[(12 + r) * 4 + cs]);
        wIF1[in]     = pack2(0.5f * Wih1[(0  + r) * 4 + cs], 0.5f * Wih1[(4  + r) * 4 + cs]);
        wGO1[in]     = pack2(       Wih1[(8  + r) * 4 + cs], 0.5f * Wih1[(12 + r) * 4 + cs]);
        wIF1[4 + in] = pack2(0.5f * Whh1[(0  + r) * 4 + cs], 0.5f * Whh1[(4  + r) * 4 + cs]);
        wGO1[4 + in] = pack2(       Whh1[(8  + r) * 4 + cs], 0.5f * Whh1[(12 + r) * 4 + cs]);
    }
    const u64 bIF0 = pack2(0.5f * (bih0[r] + bhh0[r]),
                           0.5f * (bih0[4 + r] + bhh0[4 + r]));
    const u64 bGO0 = pack2(        bih0[8 + r] + bhh0[8 + r],
                           0.5f * (bih0[12 + r] + bhh0[12 + r]));
    const u64 bIF1 = pack2(0.5f * (bih1[r] + bhh1[r]),
                           0.5f * (bih1[4 + r] + bhh1[4 + r]));
    const u64 bGO1 = pack2(        bih1[8 + r] + bhh1[8 + r],
                           0.5f * (bih1[12 + r] + bhh1[12 + r]));

    const float4* xp = (const float4*)(x + (size_t)elem * (TSEQ * 4));
    float* h2p = g_h2 + (size_t)elem * 800;

    u64 h1P[4] = {0, 0, 0, 0};
    u64 h2P[4] = {0, 0, 0, 0};
    float c1 = 0.f, c2 = 0.f;

    #pragma unroll 1
    for (int tg = 0; tg < TSEQ; tg += 4) {
        float4 xg[4];
        xg[0] = xp[tg + 0]; xg[1] = xp[tg + 1];
        xg[2] = xp[tg + 2]; xg[3] = xp[tg + 3];

        float4 st4;                               // this thread's h2 stash

        #pragma unroll
        for (int u = 0; u < 4; u++) {
            const float4 xt = xg[u];

            // ---- layer 1 ----
            u64 xP[4];
            xP[0] = pack2(xt.x, xt.x); xP[1] = pack2(xt.y, xt.y);
            xP[2] = pack2(xt.z, xt.z); xP[3] = pack2(xt.w, xt.w);
            float h1 = unit_step(xP, h1P, wIF0, wGO0, bIF0, bGO0, c1);
            {
                float a1 = __shfl_xor_sync(0xffffffffu, h1, 1);
                float a2 = __shfl_xor_sync(0xffffffffu, h1, 2);
                float a3 = __shfl_xor_sync(0xffffffffu, h1, 3);
                h1P[0] = pack2(h1, h1); h1P[1] = pack2(a1, a1);
                h1P[2] = pack2(a2, a2); h1P[3] = pack2(a3, a3);
            }

            // ---- layer 2 ----
            float h2 = unit_step(h1P, h2P, wIF1, wGO1, bIF1, bGO1, c2);
            {
                float a1 = __shfl_xor_sync(0xffffffffu, h2, 1);
                float a2 = __shfl_xor_sync(0xffffffffu, h2, 2);
                float a3 = __shfl_xor_sync(0xffffffffu, h2, 3);
                // thread with r == u stashes the quad's h2 vector (slot order)
                if (r == u) st4 = make_float4(h2, a1, a2, a3);
                h2P[0] = pack2(h2, h2); h2P[1] = pack2(a1, a1);
                h2P[2] = pack2(a2, a2); h2P[3] = pack2(a3, a3);
            }
        }

        // one coalesced STG.128 per thread per 4 steps, at step tg + r
        *(float4*)(h2p + 4 * (tg + r)) = st4;
    }
}

// =====================  kernel 2: output GEMV  =====================
__global__ void __launch_bounds__(BLOCK) gemv_kernel(
    const float* __restrict__ bout, float* __restrict__ out)
{
    const int tid  = threadIdx.x;
    const int r    = tid & 3;
    const int elem = blockIdx.x * EPB + (tid >> 2);

    u64 acc[4];
    #pragma unroll
    for (int q = 0; q < 4; q++)
        acc[q] = pack2(bout[7 * r + 2 * q], (q < 3) ? bout[7 * r + 2 * q + 1] : 0.0f);

    const float4* hp4     = (const float4*)(g_h2 + (size_t)elem * 800);
    const ulonglong2* wop = (const ulonglong2*)g_wp + (size_t)r * 2;

    #pragma unroll 1
    for (int g = 0; g < TSEQ; g += 2) {
        float4 ha = hp4[g];                      // 2 independent h2 LDGs (MLP)
        float4 hb = hp4[g + 1];

        #pragma unroll
        for (int s = 0; s < 4; s++) {
            float hv = (s == 0) ? ha.x : (s == 1) ? ha.y : (s == 2) ? ha.z : ha.w;
            u64 hp = pack2(hv, hv);
            const ulonglong2* wrow = wop + (size_t)(4 * g + s) * 8;
            ulonglong2 w0 = wrow[0];
            ulonglong2 w1 = wrow[1];
            acc[0] = fma2(hp, w0.x, acc[0]);
            acc[1] = fma2(hp, w0.y, acc[1]);
            acc[2] = fma2(hp, w1.x, acc[2]);
            acc[3] = fma2(hp, w1.y, acc[3]);
        }
        #pragma unroll
        for (int s = 0; s < 4; s++) {
            float hv = (s == 0) ? hb.x : (s == 1) ? hb.y : (s == 2) ? hb.z : hb.w;
            u64 hp = pack2(hv, hv);
            const ulonglong2* wrow = wop + (size_t)(4 * (g + 1) + s) * 8;
            ulonglong2 w0 = wrow[0];
            ulonglong2 w1 = wrow[1];
            acc[0] = fma2(hp, w0.x, acc[0]);
            acc[1] = fma2(hp, w0.y, acc[1]);
            acc[2] = fma2(hp, w1.x, acc[2]);
            acc[3] = fma2(hp, w1.y, acc[3]);
        }
    }

    float* op = out + (size_t)elem * 28 + 7 * r;
    float o0, o1, o2, o3, o4, o5, o6, dummy;
    unpack2(o0, o1, acc[0]); unpack2(o2, o3, acc[1]);
    unpack2(o4, o5, acc[2]); unpack2(o6, dummy, acc[3]);
    op[0] = o0; op[1] = o1; op[2] = o2; op[3] = o3;
    op[4] = o4; op[5] = o5; op[6] = o6;
}

extern "C" void kernel_launch(void* const* d_in, const int* in_sizes, int n_in,
                              void* d_out, int out_size)
{
    const float* x    = (const float*)d_in[0];
    const float* Wih0 = (const float*)d_in[1];
    const float* Whh0 = (const float*)d_in[2];
    const float* bih0 = (const float*)d_in[3];
    const float* bhh0 = (const float*)d_in[4];
    const float* Wih1 = (const float*)d_in[5];
    const float* Whh1 = (const float*)d_in[6];
    const float* bih1 = (const float*)d_in[7];
    const float* bhh1 = (const float*)d_in[8];
    const float* Wout = (const float*)d_in[9];
    const float* bout = (const float*)d_in[10];
    float* out = (float*)d_out;

    const int B = in_sizes[0] / (TSEQ * 4);          // 32768

    repack_kernel<<<50, 256>>>(Wout);
    lstm_kernel<<<B / EPB, BLOCK>>>(
        x, Wih0, Whh0, bih0, bhh0, Wih1, Whh1, bih1, bhh1);
    gemv_kernel<<<B / EPB, BLOCK>>>(bout, out);
}

// round 10
// speedup vs baseline: 1.9454x; 1.9454x over previous
#include <cuda_runtime.h>

#define BLOCK 256
#define TSEQ  200
#define NELEM 32768
#define NGROUPS (NELEM / 8)     // 8 elements per warp-sequence

typedef unsigned long long u64;

__device__ unsigned int g_ctr;

__global__ void init_ctr_kernel() { g_ctr = 0u; }

// ---- tanh.approx-based activations (MUFU.TANH: ~1.4e-5 abs err) ----
__device__ __forceinline__ float tanha_(float x) {
    float y; asm("tanh.approx.f32 %0, %1;" : "=f"(y) : "f"(x)); return y;
}

// ---- packed f32x2 ops ----
__device__ __forceinline__ u64 fma2(u64 a, u64 b, u64 c) {
    u64 d; asm("fma.rn.f32x2 %0, %1, %2, %3;" : "=l"(d) : "l"(a), "l"(b), "l"(c));
    return d;
}
__device__ __forceinline__ u64 pack2(float lo, float hi) {
    u64 r; asm("mov.b64 %0, {%1, %2};" : "=l"(r) : "f"(lo), "f"(hi)); return r;
}
__device__ __forceinline__ void unpack2(float& lo, float& hi, u64 v) {
    asm("mov.b64 {%0, %1}, %2;" : "=f"(lo), "=f"(hi) : "l"(v));
}

// smem: Wout packs. [800 phys-col][4 r][4 qpack] u64 = 12800 u64 = 100 KB.
// phys col (4t+s) for r-class r holds logical column 4t + (s^r) (slot s = unit r^s).
#define SM_U64 12800

// one LSTM unit step. gIF lanes = (i,f), gGO lanes = (g,o).
// i/f/o rows and biases PRE-SCALED by 0.5 -> sigmoid = fma(tanh, .5, .5).
__device__ __forceinline__ float unit_step(
    const u64* __restrict__ inA, const u64* __restrict__ inB,
    const u64* __restrict__ wIF, const u64* __restrict__ wGO,
    u64 bIF, u64 bGO, float& c)
{
    u64 gIF = bIF, gGO = bGO;
    #pragma unroll
    for (int in = 0; in < 4; in++) {
        gIF = fma2(inA[in], wIF[in], gIF);
        gGO = fma2(inA[in], wGO[in], gGO);
    }
    #pragma unroll
    for (int in = 0; in < 4; in++) {
        gIF = fma2(inB[in], wIF[4 + in], gIF);
        gGO = fma2(inB[in], wGO[4 + in], gGO);
    }
    float iv, fv, gv, ov;
    unpack2(iv, fv, gIF);
    unpack2(gv, ov, gGO);
    float ti = tanha_(iv), tf = tanha_(fv), tg = tanha_(gv), to = tanha_(ov);
    float si = fmaf(ti, 0.5f, 0.5f);
    float sf = fmaf(tf, 0.5f, 0.5f);
    float so = fmaf(to, 0.5f, 0.5f);
    c = fmaf(sf, c, si * tg);
    return so * tanha_(c);
}

__global__ void __launch_bounds__(BLOCK, 2) lstm_fused_kernel(
    const float* __restrict__ x,
    const float* __restrict__ Wih0, const float* __restrict__ Whh0,
    const float* __restrict__ bih0, const float* __restrict__ bhh0,
    const float* __restrict__ Wih1, const float* __restrict__ Whh1,
    const float* __restrict__ bih1, const float* __restrict__ bhh1,
    const float* __restrict__ Wout, const float* __restrict__ bout,
    float* __restrict__ out)
{
    extern __shared__ u64 smu[];
    const int tid  = threadIdx.x;
    const int lane = tid & 31;
    const int r    = tid & 3;                     // unit index / output quarter

    // ---- stage Wout packs with per-r column permutation (once per CTA) ----
    for (int idx = tid; idx < SM_U64; idx += BLOCK) {
        int c  = idx >> 4;
        int r4 = (idx >> 2) & 3;
        int q  = idx & 3;
        int srcc = (c & ~3) | ((c & 3) ^ r4);     // logical column for this r-class
        int row0 = 7 * r4 + 2 * q;                // rows 7r .. 7r+6 (q=3 hi is dummy)
        float lo = Wout[row0 * 800 + srcc];
        float hi = (q < 3) ? Wout[(row0 + 1) * 800 + srcc] : 0.0f;
        smu[idx] = pack2(lo, hi);
    }
    __syncthreads();

    // ---- gate weights -> registers, 0.5-prescaled for sigmoid gates ----
    u64 wIF0[8], wGO0[8], wIF1[8], wGO1[8];
    #pragma unroll
    for (int in = 0; in < 4; in++) {
        int cs = r ^ in;                           // permuted column for h slots
        wIF0[in]     = pack2(0.5f * Wih0[(0  + r) * 4 + in], 0.5f * Wih0[(4  + r) * 4 + in]);
        wGO0[in]     = pack2(       Wih0[(8  + r) * 4 + in], 0.5f * Wih0[(12 + r) * 4 + in]);
        wIF0[4 + in] = pack2(0.5f * Whh0[(0  + r) * 4 + cs], 0.5f * Whh0[(4  + r) * 4 + cs]);
        wGO0[4 + in] = pack2(       Whh0[(8  + r) * 4 + cs], 0.5f * Whh0[(12 + r) * 4 + cs]);
        wIF1[in]     = pack2(0.5f * Wih1[(0  + r) * 4 + cs], 0.5f * Wih1[(4  + r) * 4 + cs]);
        wGO1[in]     = pack2(       Wih1[(8  + r) * 4 + cs], 0.5f * Wih1[(12 + r) * 4 + cs]);
        wIF1[4 + in] = pack2(0.5f * Whh1[(0  + r) * 4 + cs], 0.5f * Whh1[(4  + r) * 4 + cs]);
        wGO1[4 + in] = pack2(       Whh1[(8  + r) * 4 + cs], 0.5f * Whh1[(12 + r) * 4 + cs]);
    }
    const u64 bIF0 = pack2(0.5f * (bih0[r] + bhh0[r]),
                           0.5f * (bih0[4 + r] + bhh0[4 + r]));
    const u64 bGO0 = pack2(        bih0[8 + r] + bhh0[8 + r],
                           0.5f * (bih0[12 + r] + bhh0[12 + r]));
    const u64 bIF1 = pack2(0.5f * (bih1[r] + bhh1[r]),
                           0.5f * (bih1[4 + r] + bhh1[4 + r]));
    const u64 bGO1 = pack2(        bih1[8 + r] + bhh1[8 + r],
                           0.5f * (bih1[12 + r] + bhh1[12 + r]));

    const u64 accInit0 = pack2(bout[7 * r + 0], bout[7 * r + 1]);
    const u64 accInit1 = pack2(bout[7 * r + 2], bout[7 * r + 3]);
    const u64 accInit2 = pack2(bout[7 * r + 4], bout[7 * r + 5]);
    const u64 accInit3 = pack2(bout[7 * r + 6], 0.0f);

    const ulonglong2* wop = (const ulonglong2*)smu + (size_t)r * 2;

    // ---- persistent warp-level work stealing over 8-element sequences ----
    for (;;) {
        unsigned int g;
        if (lane == 0) g = atomicAdd(&g_ctr, 1u);
        g = __shfl_sync(0xffffffffu, g, 0);
        if (g >= NGROUPS) break;

        const int elem = (int)g * 8 + (lane >> 2);
        const float4* xp = (const float4*)(x + (size_t)elem * (TSEQ * 4));

        u64 h1P[4] = {0, 0, 0, 0};                // pack2(h1s[s], h1s[s])
        u64 h2P[4] = {0, 0, 0, 0};
        float c1 = 0.f, c2 = 0.f;
        u64 acc[4] = {accInit0, accInit1, accInit2, accInit3};

        #pragma unroll 1
        for (int tg = 0; tg < TSEQ; tg += 4) {
            float4 xg[4];
            xg[0] = xp[tg + 0]; xg[1] = xp[tg + 1];
            xg[2] = xp[tg + 2]; xg[3] = xp[tg + 3];

            #pragma unroll
            for (int u = 0; u < 4; u++) {
                const int t = tg + u;
                const float4 xt = xg[u];

                // ---- layer 1 ----
                u64 xP[4];
                xP[0] = pack2(xt.x, xt.x); xP[1] = pack2(xt.y, xt.y);
                xP[2] = pack2(xt.z, xt.z); xP[3] = pack2(xt.w, xt.w);
                float h1 = unit_step(xP, h1P, wIF0, wGO0, bIF0, bGO0, c1);
                {
                    float a1 = __shfl_xor_sync(0xffffffffu, h1, 1);
                    float a2 = __shfl_xor_sync(0xffffffffu, h1, 2);
                    float a3 = __shfl_xor_sync(0xffffffffu, h1, 3);
                    h1P[0] = pack2(h1, h1); h1P[1] = pack2(a1, a1);
                    h1P[2] = pack2(a2, a2); h1P[3] = pack2(a3, a3);
                }

                // ---- layer 2 ----
                float h2 = unit_step(h1P, h2P, wIF1, wGO1, bIF1, bGO1, c2);
                {
                    float a1 = __shfl_xor_sync(0xffffffffu, h2, 1);
                    float a2 = __shfl_xor_sync(0xffffffffu, h2, 2);
                    float a3 = __shfl_xor_sync(0xffffffffu, h2, 3);
                    h2P[0] = pack2(h2, h2); h2P[1] = pack2(a1, a1);
                    h2P[2] = pack2(a2, a2); h2P[3] = pack2(a3, a3);
                }

                // ---- GEMV: reuses h2P ----
                #pragma unroll
                for (int s = 0; s < 4; s++) {
                    const ulonglong2* wrow = wop + (size_t)(4 * t + s) * 8;
                    ulonglong2 w0 = wrow[0];
                    ulonglong2 w1 = wrow[1];
                    acc[0] = fma2(h2P[s], w0.x, acc[0]);
                    acc[1] = fma2(h2P[s], w0.y, acc[1]);
                    acc[2] = fma2(h2P[s], w1.x, acc[2]);
                    acc[3] = fma2(h2P[s], w1.y, acc[3]);
                }
            }
        }

        // ---- write 7 outputs for this element ----
        float* op = out + (size_t)elem * 28 + 7 * r;
        float o0, o1, o2, o3, o4, o5, o6, dummy;
        unpack2(o0, o1, acc[0]); unpack2(o2, o3, acc[1]);
        unpack2(o4, o5, acc[2]); unpack2(o6, dummy, acc[3]);
        op[0] = o0; op[1] = o1; op[2] = o2; op[3] = o3;
        op[4] = o4; op[5] = o5; op[6] = o6;
    }
}

extern "C" void kernel_launch(void* const* d_in, const int* in_sizes, int n_in,
                              void* d_out, int out_size)
{
    const float* x    = (const float*)d_in[0];
    const float* Wih0 = (const float*)d_in[1];
    const float* Whh0 = (const float*)d_in[2];
    const float* bih0 = (const float*)d_in[3];
    const float* bhh0 = (const float*)d_in[4];
    const float* Wih1 = (const float*)d_in[5];
    const float* Whh1 = (const float*)d_in[6];
    const float* bih1 = (const float*)d_in[7];
    const float* bhh1 = (const float*)d_in[8];
    const float* Wout = (const float*)d_in[9];
    const float* bout = (const float*)d_in[10];
    float* out = (float*)d_out;

    const int smem_bytes = SM_U64 * sizeof(u64);     // 102400 B

    // persistent grid: 2 CTAs per SM (work-stealing tolerates any SM count)
    int nsm = 148;
    cudaDeviceGetAttribute(&nsm, cudaDevAttrMultiProcessorCount, 0);
    const int grid = 2 * nsm;

    cudaFuncSetAttribute(lstm_fused_kernel,
                         cudaFuncAttributeMaxDynamicSharedMemorySize, smem_bytes);

    init_ctr_kernel<<<1, 1>>>();
    lstm_fused_kernel<<<grid, BLOCK, smem_bytes>>>(
        x, Wih0, Whh0, bih0, bhh0, Wih1, Whh1, bih1, bhh1, Wout, bout, out);
}